// round 2
// baseline (speedup 1.0000x reference)
#include <cuda_runtime.h>
#include <cuda_bf16.h>

// CSPN 5x5 propagation, B=4, H=352, W=1216.
// out[b,y,x] = sum_{t=0..24} w[b,t,y+2,x+2] * v_t
//   v_t = h0[b,y,x]                       if t == 12 (center)
//       = hn_zeropad[b, y+2-t/5, x+2-t%5] otherwise
//
// DRAM-bound design (~192 MB traffic, floor ~27us):
//  - weights streamed once, 2 pixels/thread via aligned LDG.64 (padded row
//    width 1220 % 4 == 0, +2 col offset keeps 8B alignment)
//  - hn neighbor reuse captured in a smem halo tile; per 5x1 tap row the
//    6-value register window serves both pixels with 3x LDS.64
//  - 64x8 tile, 32x8 block: exact 19x44x4 grid, warp == row, conflict-free

#define KW 5
#define BB 4
#define HH 352
#define WW 1216
#define HP (HH + KW - 1)   // 356
#define WP (WW + KW - 1)   // 1220
#define HPWP (HP * WP)
#define TXN 32             // threads in x
#define TY 8
#define TILE_W (TXN * 2)   // 64 pixels
#define SROWS (TY + 4)     // 12
#define SCOLS (TILE_W + 4) // 68

__global__ __launch_bounds__(TXN * TY)
void cspn_kernel(const float* __restrict__ gw,
                 const float* __restrict__ hn,
                 const float* __restrict__ h0,
                 float* __restrict__ out)
{
    __shared__ float s[SROWS][SCOLS];

    const int b   = blockIdx.z;
    const int bx0 = blockIdx.x * TILE_W;
    const int by0 = blockIdx.y * TY;
    const int tx  = threadIdx.x;
    const int ty  = threadIdx.y;
    const int tid = ty * TXN + tx;

    // ---- load hn halo tile (zero-padded) into smem ----
    const float* hnb = hn + b * (HH * WW);
    #pragma unroll
    for (int idx = tid; idx < SROWS * SCOLS; idx += TXN * TY) {
        const int r  = idx / SCOLS;
        const int c  = idx - r * SCOLS;
        const int gy = by0 - 2 + r;
        const int gx = bx0 - 2 + c;
        float v = 0.0f;
        if (gy >= 0 && gy < HH && gx >= 0 && gx < WW)
            v = hnb[gy * WW + gx];
        s[r][c] = v;
    }
    __syncthreads();

    const int y   = by0 + ty;
    const int tx2 = tx * 2;
    const int x0  = bx0 + tx2;          // even -> all float2 accesses aligned

    // weight pointer for tap 0, pixel pair: w[b, 0, y+2, x0+2]
    const float* wp = gw + ((size_t)(b * 25) * HP + (y + 2)) * WP + (x0 + 2);

    const float2 h0v = *(const float2*)(h0 + ((size_t)b * HH + y) * WW + x0);

    float acc0 = 0.0f, acc1 = 0.0f;

    #pragma unroll
    for (int dy = 0; dy < KW; dy++) {
        const int r = ty + 4 - dy;

        // 6-value register window: cols [tx2 .. tx2+5] of smem row r
        const float2 ra = *(const float2*)&s[r][tx2];
        const float2 rb = *(const float2*)&s[r][tx2 + 2];
        const float2 rc = *(const float2*)&s[r][tx2 + 4];
        const float rv[6] = { ra.x, ra.y, rb.x, rb.y, rc.x, rc.y };

        #pragma unroll
        for (int dx = 0; dx < KW; dx++) {
            const int t = dy * KW + dx;
            const float2 w = *(const float2*)(wp + (size_t)t * HPWP);
            float v0 = rv[4 - dx];
            float v1 = rv[5 - dx];
            if (t == 12) { v0 = h0v.x; v1 = h0v.y; }
            acc0 = fmaf(w.x, v0, acc0);
            acc1 = fmaf(w.y, v1, acc1);
        }
    }

    *(float2*)(out + ((size_t)b * HH + y) * WW + x0) = make_float2(acc0, acc1);
}

extern "C" void kernel_launch(void* const* d_in, const int* in_sizes, int n_in,
                              void* d_out, int out_size)
{
    const float* gw = (const float*)d_in[0];  // guide_weight [4,25,356,1220]
    const float* hn = (const float*)d_in[1];  // hn [4,1,352,1216]
    const float* h0 = (const float*)d_in[2];  // h0 [4,1,352,1216]
    float* out = (float*)d_out;               // [4,1,352,1216]

    dim3 block(TXN, TY);
    dim3 grid(WW / TILE_W, HH / TY, BB);      // 19 x 44 x 4, exact tiling
    cspn_kernel<<<grid, block>>>(gw, hn, h0, out);
}

// round 3
// speedup vs baseline: 1.0692x; 1.0692x over previous
#include <cuda_runtime.h>
#include <cuda_bf16.h>

// CSPN 5x5 propagation, B=4, H=352, W=1216.
// out[b,y,x] = sum_{t=0..24} w[b,t,y+2,x+2] * v_t
//   v_t = h0[b,y,x]                       if t == 12 (center)
//       = hn_zeropad[b, y+2-t/5, x+2-t%5] otherwise
//
// R3 design: NO shared memory, NO __syncthreads. All hn neighbor reads go
// through L1 (heavy intra-block reuse -> L1 hits; cross-block -> L2 hits).
// Every thread issues 41 independent LDG.64 (25 weight taps + 15 hn window
// + 1 h0) front-batched with nothing serializing ahead of them, so DRAM
// demand starts at cycle 0 of every block. Traffic stays at the ~192 MB
// minimum; goal is raising achieved HBM BW from 5.86 toward ~7.3 TB/s.
//
// Alignment: x0 even and W even => each 6-wide hn window is 3 float2 loads
// that are each fully in-bounds or fully out-of-bounds (one predicate per
// load, no lane-partial cases).

#define KW 5
#define BB 4
#define HH 352
#define WW 1216
#define HP (HH + KW - 1)   // 356
#define WP (WW + KW - 1)   // 1220
#define HPWP (HP * WP)
#define TXN 32             // threads in x (each handles 2 pixels)
#define TY 8
#define TILE_W (TXN * 2)   // 64 pixels

__global__ __launch_bounds__(TXN * TY)
void cspn_kernel(const float* __restrict__ gw,
                 const float* __restrict__ hn,
                 const float* __restrict__ h0,
                 float* __restrict__ out)
{
    const int b   = blockIdx.z;
    const int x0  = blockIdx.x * TILE_W + threadIdx.x * 2;  // even
    const int y   = blockIdx.y * TY + threadIdx.y;

    const float* hnb = hn + (size_t)b * (HH * WW);

    // weight pointer for tap 0, pixel pair: w[b, 0, y+2, x0+2]
    const float* wp = gw + ((size_t)(b * 25) * HP + (y + 2)) * WP + (x0 + 2);

    const float2 h0v = *(const float2*)(h0 + ((size_t)b * HH + y) * WW + x0);

    const bool xlo = (x0 >= 2);          // window col x0-2 in bounds
    const bool xhi = (x0 <= WW - 4);     // window cols x0+2,x0+3 in bounds

    float acc0 = 0.0f, acc1 = 0.0f;

    #pragma unroll
    for (int dy = 0; dy < KW; dy++) {
        const int yy   = y + 2 - dy;                 // hn source row for this tap row
        const bool yok = (yy >= 0) && (yy < HH);
        const float* rowp = hnb + (size_t)yy * WW;

        float2 a = make_float2(0.0f, 0.0f);
        float2 bb = make_float2(0.0f, 0.0f);
        float2 c = make_float2(0.0f, 0.0f);
        if (yok) {
            if (xlo) a = __ldg((const float2*)(rowp + x0 - 2));
            bb = __ldg((const float2*)(rowp + x0));
            if (xhi) c = __ldg((const float2*)(rowp + x0 + 2));
        }
        const float rv[6] = { a.x, a.y, bb.x, bb.y, c.x, c.y };

        #pragma unroll
        for (int dx = 0; dx < KW; dx++) {
            const int t = dy * KW + dx;
            const float2 w = __ldg((const float2*)(wp + (size_t)t * HPWP));
            float v0 = rv[4 - dx];
            float v1 = rv[5 - dx];
            if (t == 12) { v0 = h0v.x; v1 = h0v.y; }
            acc0 = fmaf(w.x, v0, acc0);
            acc1 = fmaf(w.y, v1, acc1);
        }
    }

    *(float2*)(out + ((size_t)b * HH + y) * WW + x0) = make_float2(acc0, acc1);
}

extern "C" void kernel_launch(void* const* d_in, const int* in_sizes, int n_in,
                              void* d_out, int out_size)
{
    const float* gw = (const float*)d_in[0];  // guide_weight [4,25,356,1220]
    const float* hn = (const float*)d_in[1];  // hn [4,1,352,1216]
    const float* h0 = (const float*)d_in[2];  // h0 [4,1,352,1216]
    float* out = (float*)d_out;               // [4,1,352,1216]

    dim3 block(TXN, TY);
    dim3 grid(WW / TILE_W, HH / TY, BB);      // 19 x 44 x 4, exact tiling
    cspn_kernel<<<grid, block>>>(gw, hn, h0, out);
}